// round 12
// baseline (speedup 1.0000x reference)
#include <cuda_runtime.h>
#include <cuda_bf16.h>
#include <math.h>
#include <float.h>
#include <stdint.h>

#define BATCH 96
#define NQ 35
#define LP 180
#define HID 768
#define DIM 128

#define QTILES 27            // ceil(3360/128)
#define MQ (BATCH * NQ)      // 3360
#define MP (BATCH * LP)      // 17280

// ===================== scratch (no allocation allowed) =====================
__device__ float g_q[MQ * DIM];
__device__ float g_pos[MP * DIM];
__device__ float g_neg[MP * DIM];
__device__ float g_pmask[BATCH * LP];
__device__ float g_nmask[BATCH * LP];
__device__ int   g_mask_mode;
__device__ float g_qinv[BATCH * DIM];
__device__ float g_pinv[2][BATCH * DIM];
__device__ float g_part[QTILES][2][BATCH][5];

// pre-converted bf16 tiles, ldmatrix-swizzled
__device__ unsigned char g_qt[2][QTILES][32768];              // flat q rows, full-K 256B rows
__device__ unsigned char g_pt[2][2][BATCH][2][2][12288];      // [hi/lo][side][bp][half_l][half_k]
__device__ unsigned char g_wt[2][6][32768];                   // W^T per k-chunk, 256B rows

// ===================== helpers =====================
__device__ __forceinline__ uint32_t smem_u32(const void* p) {
    uint32_t a;
    asm("{ .reg .u64 t; cvta.to.shared.u64 t, %1; cvt.u32.u64 %0, t; }" : "=r"(a) : "l"(p));
    return a;
}

#define LDSM_X4(r0, r1, r2, r3, addr) \
    asm volatile("ldmatrix.sync.aligned.m8n8.x4.shared.b16 {%0,%1,%2,%3}, [%4];" \
        : "=r"(r0), "=r"(r1), "=r"(r2), "=r"(r3) : "r"(addr))

#define MMA_BF16(c, a, b) \
    asm volatile("mma.sync.aligned.m16n8k16.row.col.f32.bf16.bf16.f32 " \
        "{%0,%1,%2,%3}, {%4,%5,%6,%7}, {%8,%9}, {%0,%1,%2,%3};" \
        : "+f"((c)[0]), "+f"((c)[1]), "+f"((c)[2]), "+f"((c)[3]) \
        : "r"((a)[0]), "r"((a)[1]), "r"((a)[2]), "r"((a)[3]), \
          "r"((b)[0]), "r"((b)[1]))

__device__ __forceinline__ uint32_t pack_bf16(float f0, float f1) {
    uint16_t u0 = __bfloat16_as_ushort(__float2bfloat16(f0));
    uint16_t u1 = __bfloat16_as_ushort(__float2bfloat16(f1));
    return (uint32_t)u0 | ((uint32_t)u1 << 16);
}
__device__ __forceinline__ float bf16_res(float f) {
    return f - __bfloat162float(__float2bfloat16(f));
}
__device__ __forceinline__ void pack8(const float4& v0, const float4& v1,
                                      uint4& hv, uint4& lv) {
    hv.x = pack_bf16(v0.x, v0.y); hv.y = pack_bf16(v0.z, v0.w);
    hv.z = pack_bf16(v1.x, v1.y); hv.w = pack_bf16(v1.z, v1.w);
    lv.x = pack_bf16(bf16_res(v0.x), bf16_res(v0.y));
    lv.y = pack_bf16(bf16_res(v0.z), bf16_res(v0.w));
    lv.z = pack_bf16(bf16_res(v1.x), bf16_res(v1.y));
    lv.w = pack_bf16(bf16_res(v1.z), bf16_res(v1.w));
}
__device__ __forceinline__ unsigned enc_f(float x) {
    unsigned u = __float_as_uint(x);
    return (u & 0x80000000u) ? ~u : (u | 0x80000000u);
}
__device__ __forceinline__ float dec_f(unsigned e) {
    return (e & 0x80000000u) ? __uint_as_float(e ^ 0x80000000u)
                             : __uint_as_float(~e);
}

// ===================== mask dtype detection =====================
__global__ void detect_mode_kernel(const unsigned int* __restrict__ m) {
    __shared__ int s_bf16, s_f32, s_gt1;
    if (threadIdx.x == 0) { s_bf16 = 0; s_f32 = 0; s_gt1 = 0; }
    __syncthreads();
    int lbf = 0, lf = 0, lg = 0;
    for (int i = threadIdx.x; i < (BATCH * LP) / 4; i += blockDim.x) {
        unsigned int w = m[i];
        if (w == 0x3F803F80u) lbf = 1;
        else if (w == 0x3F800000u) lf = 1;
        else if (w > 1u) lg = 1;
    }
    if (lbf) s_bf16 = 1;
    if (lf)  s_f32 = 1;
    if (lg)  s_gt1 = 1;
    __syncthreads();
    if (threadIdx.x == 0) {
        int mode;
        if (s_bf16)      mode = 3;
        else if (s_f32)  mode = 2;
        else if (s_gt1)  mode = 0;
        else             mode = 1;
        g_mask_mode = mode;
    }
}

__global__ void expand_mask_kernel(const void* __restrict__ pm, const void* __restrict__ nm) {
    int idx = blockIdx.x * blockDim.x + threadIdx.x;
    if (idx >= BATCH * LP) return;
    int mode = g_mask_mode;
    float pv, nv;
    if (mode == 0) {
        pv = ((const unsigned char*)pm)[idx] ? 1.f : 0.f;
        nv = ((const unsigned char*)nm)[idx] ? 1.f : 0.f;
    } else if (mode == 1) {
        pv = ((const int*)pm)[idx] ? 1.f : 0.f;
        nv = ((const int*)nm)[idx] ? 1.f : 0.f;
    } else if (mode == 2) {
        pv = (((const float*)pm)[idx] != 0.f) ? 1.f : 0.f;
        nv = (((const float*)nm)[idx] != 0.f) ? 1.f : 0.f;
    } else {
        pv = (__bfloat162float(((const __nv_bfloat16*)pm)[idx]) != 0.f) ? 1.f : 0.f;
        nv = (__bfloat162float(((const __nv_bfloat16*)nm)[idx]) != 0.f) ? 1.f : 0.f;
    }
    g_pmask[idx] = pv;
    g_nmask[idx] = nv;
}

// ===================== W^T -> bf16 hi/lo swizzled tiles =====================
__global__ void wt_convert_kernel(const float* __restrict__ W) {
    int idx = blockIdx.x * blockDim.x + threadIdx.x;
    if (idx >= 6 * 128 * 16) return;
    int kc = idx >> 11;
    int rem = idx & 2047;
    int d = rem >> 4, c = rem & 15;
    int h0 = kc * 128 + c * 8;
    float w[8];
    #pragma unroll
    for (int e = 0; e < 8; e++) w[e] = W[(size_t)(h0 + e) * DIM + d];
    float4 v0 = make_float4(w[0], w[1], w[2], w[3]);
    float4 v1 = make_float4(w[4], w[5], w[6], w[7]);
    uint4 hv, lv; pack8(v0, v1, hv, lv);
    uint32_t off = (uint32_t)d * 256u + (uint32_t)(c ^ (d & 7)) * 16u;
    *(uint4*)&g_wt[0][kc][off] = hv;
    *(uint4*)&g_wt[1][kc][off] = lv;
}

// ===================== merged projection GEMM (half-K phases, 64KB smem) =====
#define PJ_AH 0
#define PJ_AL 16384
#define PJ_BH 32768
#define PJ_BL 49152
#define PJ_SMEM 65536

__global__ __launch_bounds__(256, 2) void proj_mma_kernel(
    const float* __restrict__ Aq, const float* __restrict__ Ap,
    const float* __restrict__ An, const float* __restrict__ bias)
{
    extern __shared__ char sm[];
    uint32_t smb = smem_u32(sm);
    int tid = threadIdx.x;
    int lane = tid & 31;
    int wid = tid >> 5;
    int mw = wid >> 1;
    int nw = wid & 1;

    int bx = blockIdx.x;
    const float* A; float* out; int row0, M;
    if (bx < QTILES)         { A = Aq; out = g_q;   row0 = bx * 128;              M = MQ; }
    else if (bx < QTILES+135){ A = Ap; out = g_pos; row0 = (bx-QTILES) * 128;     M = MP; }
    else                     { A = An; out = g_neg; row0 = (bx-QTILES-135) * 128; M = MP; }

    float cfr[2][8][4];
    #pragma unroll
    for (int mi = 0; mi < 2; mi++)
        #pragma unroll
        for (int t = 0; t < 8; t++)
            #pragma unroll
            for (int u = 0; u < 4; u++) cfr[mi][t][u] = 0.f;

    int a_row  = lane & 15;
    int a_chnk = lane >> 4;
    int b_row  = ((lane & 16) >> 1) + (lane & 7);
    int b_chnk = (lane >> 3) & 1;

    for (int kc = 0; kc < 6; kc++) {
        #pragma unroll
        for (int kh = 0; kh < 2; kh++) {
            __syncthreads();
            // copy W^T k-half: contiguous 128B slice of each 256B row
            {
                const unsigned char* bh = &g_wt[0][kc][0];
                const unsigned char* bl = &g_wt[1][kc][0];
                for (int i = tid; i < 1024; i += 256) {
                    int r = i >> 3, x = i & 7;
                    uint32_t so = (uint32_t)r * 256u + (uint32_t)kh * 128u + (uint32_t)x * 16u;
                    uint32_t dofs = (uint32_t)r * 128u + (uint32_t)x * 16u;
                    *(uint4*)(sm + PJ_BH + dofs) = *(const uint4*)(bh + so);
                    *(uint4*)(sm + PJ_BL + dofs) = *(const uint4*)(bl + so);
                }
            }
            // convert A k-half
            for (int i = tid; i < 1024; i += 256) {
                int r = i >> 3, c = i & 7;
                int gr = row0 + r;
                float4 v0 = make_float4(0.f, 0.f, 0.f, 0.f), v1 = v0;
                if (gr < M) {
                    const float* ar = A + (size_t)gr * HID + kc * 128 + kh * 64 + c * 8;
                    v0 = *(const float4*)ar;
                    v1 = *(const float4*)(ar + 4);
                }
                uint4 hv, lv; pack8(v0, v1, hv, lv);
                uint32_t off = (uint32_t)r * 128u + (uint32_t)(c ^ (r & 7)) * 16u;
                *(uint4*)(sm + PJ_AH + off) = hv;
                *(uint4*)(sm + PJ_AL + off) = lv;
            }
            __syncthreads();

            #pragma unroll
            for (int k = 0; k < 4; k++) {
                uint32_t aqh[2][4], aql[2][4], bph[8][2], bpl[8][2];
                #pragma unroll
                for (int mi = 0; mi < 2; mi++) {
                    int row = 32 * mw + 16 * mi + a_row;
                    uint32_t off = (uint32_t)row * 128u
                                 + (uint32_t)((2 * k + a_chnk) ^ (row & 7)) * 16u;
                    LDSM_X4(aqh[mi][0], aqh[mi][1], aqh[mi][2], aqh[mi][3], smb + PJ_AH + off);
                    LDSM_X4(aql[mi][0], aql[mi][1], aql[mi][2], aql[mi][3], smb + PJ_AL + off);
                }
                #pragma unroll
                for (int j = 0; j < 4; j++) {
                    int row = 64 * nw + 16 * j + b_row;
                    uint32_t off = (uint32_t)row * 128u
                                 + (uint32_t)((2 * k + b_chnk) ^ (row & 7)) * 16u;
                    LDSM_X4(bph[2*j][0], bph[2*j][1], bph[2*j+1][0], bph[2*j+1][1], smb + PJ_BH + off);
                    LDSM_X4(bpl[2*j][0], bpl[2*j][1], bpl[2*j+1][0], bpl[2*j+1][1], smb + PJ_BL + off);
                }
                #pragma unroll
                for (int mi = 0; mi < 2; mi++)
                    #pragma unroll
                    for (int t = 0; t < 8; t++) {
                        MMA_BF16(cfr[mi][t], aqh[mi], bph[t]);
                        MMA_BF16(cfr[mi][t], aqh[mi], bpl[t]);
                        MMA_BF16(cfr[mi][t], aql[mi], bph[t]);
                    }
            }
        }
    }

    #pragma unroll
    for (int mi = 0; mi < 2; mi++) {
        int r0 = row0 + 32 * mw + 16 * mi + (lane >> 2);
        #pragma unroll
        for (int t = 0; t < 8; t++) {
            int col = 64 * nw + 8 * t + 2 * (lane & 3);
            float b0 = bias[col], b1 = bias[col + 1];
            if (r0 < M) {
                out[(size_t)r0 * DIM + col]     = cfr[mi][t][0] + b0;
                out[(size_t)r0 * DIM + col + 1] = cfr[mi][t][1] + b1;
            }
            if (r0 + 8 < M) {
                out[(size_t)(r0 + 8) * DIM + col]     = cfr[mi][t][2] + b0;
                out[(size_t)(r0 + 8) * DIM + col + 1] = cfr[mi][t][3] + b1;
            }
        }
    }
}

// ===================== norm factors =====================
__global__ void norm_factor_kernel() {
    int idx = blockIdx.x * blockDim.x + threadIdx.x;
    if (idx >= BATCH * DIM) return;
    int which = blockIdx.y;
    const float* src = (which == 0) ? g_q : (which == 1) ? g_pos : g_neg;
    int L = (which == 0) ? NQ : LP;
    int b = idx >> 7, d = idx & 127;
    const float* base = src + (size_t)b * L * DIM + d;
    float s = 0.f;
    for (int l = 0; l < L; l++) { float v = base[(size_t)l * DIM]; s += v * v; }
    float inv = 1.f / fmaxf(sqrtf(s), 1e-12f);
    if (which == 0) g_qinv[idx] = inv;
    else            g_pinv[which - 1][idx] = inv;
}

// ===================== tile converters (apply norm inline) =====================
__global__ void qt_convert_kernel() {
    int t = blockIdx.x;
    int tid = threadIdx.x;
    for (int i = tid; i < 128 * 16; i += 256) {
        int r = i >> 4, c = i & 15;
        int gr = t * 128 + r;
        float4 v0 = make_float4(0.f, 0.f, 0.f, 0.f), v1 = v0;
        if (gr < MQ) {
            int b = gr / 35;
            const float* qrow = g_q + (size_t)gr * DIM + c * 8;
            const float* iv = g_qinv + b * DIM + c * 8;
            float4 r0 = *(const float4*)qrow;
            float4 r1 = *(const float4*)(qrow + 4);
            float4 i0 = *(const float4*)iv;
            float4 i1 = *(const float4*)(iv + 4);
            v0 = make_float4(r0.x * i0.x, r0.y * i0.y, r0.z * i0.z, r0.w * i0.w);
            v1 = make_float4(r1.x * i1.x, r1.y * i1.y, r1.z * i1.z, r1.w * i1.w);
        }
        uint4 hv, lv; pack8(v0, v1, hv, lv);
        uint32_t off = (uint32_t)r * 256u + (uint32_t)(c ^ (r & 7)) * 16u;
        *(uint4*)&g_qt[0][t][off] = hv;
        *(uint4*)&g_qt[1][t][off] = lv;
    }
}

// p: half-K tile layout (128B rows)
__global__ void pt_convert_kernel() {
    int bp = blockIdx.x, h = blockIdx.y, z = blockIdx.z;
    const float* P = z ? g_neg : g_pos;
    const float* inv = g_pinv[z] + bp * DIM;
    int tid = threadIdx.x;
    int l0 = h * 84;
    for (int i = tid; i < 96 * 16; i += 256) {
        int r = i >> 4, c = i & 15;
        const float* prow = P + (size_t)(bp * LP + l0 + r) * DIM + c * 8;
        float4 r0 = *(const float4*)prow;
        float4 r1 = *(const float4*)(prow + 4);
        float4 i0 = *(const float4*)(inv + c * 8);
        float4 i1 = *(const float4*)(inv + c * 8 + 4);
        float4 v0 = make_float4(r0.x * i0.x, r0.y * i0.y, r0.z * i0.z, r0.w * i0.w);
        float4 v1 = make_float4(r1.x * i1.x, r1.y * i1.y, r1.z * i1.z, r1.w * i1.w);
        uint4 hv, lv; pack8(v0, v1, hv, lv);
        int kh = c >> 3;
        uint32_t off = (uint32_t)r * 128u + (uint32_t)((c & 7) ^ (r & 7)) * 16u;
        *(uint4*)&g_pt[0][z][bp][h][kh][off] = hv;
        *(uint4*)&g_pt[1][z][bp][h][kh][off] = lv;
    }
}

// ===================== mma.sync MaxSim (88KB smem, 2 CTAs/SM) =====================
#define QH_OFF 0
#define QL_OFF 32768
#define PH_OFF 65536
#define PL_OFF 77824
#define MS_SMEM 90112

__global__ __launch_bounds__(256, 2) void maxsim_mma_kernel(
    const float* __restrict__ Mpos, const float* __restrict__ Mneg)
{
    extern __shared__ char sm[];
    uint32_t smb = smem_u32(sm);
    __shared__ float    bias_s[96];
    __shared__ unsigned rowmax[128];

    int bp = blockIdx.x, qt = blockIdx.y, z = blockIdx.z;
    const float* Mf = z ? Mneg : Mpos;
    int tid  = threadIdx.x;
    int lane = tid & 31;
    int wid  = tid >> 5;
    int mw = wid >> 1;
    int nw = wid & 1;

    if (tid < 128) rowmax[tid] = 0u;

    // q tile: full-K, loaded once
    {
        const uint4* qh = (const uint4*)&g_qt[0][qt][0];
        const uint4* ql = (const uint4*)&g_qt[1][qt][0];
        for (int i = tid; i < 2048; i += 256) {
            *(uint4*)(sm + QH_OFF + i * 16) = qh[i];
            *(uint4*)(sm + QL_OFF + i * 16) = ql[i];
        }
    }

    int a_row  = lane & 15;
    int a_chnk = lane >> 4;
    int b_row  = ((lane & 16) >> 1) + (lane & 7);
    int b_chnk = (lane >> 3) & 1;

    #pragma unroll
    for (int h = 0; h < 2; h++) {
        int l0 = h * 84;

        float cfr[2][6][4];
        #pragma unroll
        for (int mi = 0; mi < 2; mi++)
            #pragma unroll
            for (int t = 0; t < 6; t++)
                #pragma unroll
                for (int u = 0; u < 4; u++) cfr[mi][t][u] = 0.f;

        #pragma unroll
        for (int kh = 0; kh < 2; kh++) {
            __syncthreads();
            {
                const uint4* ph = (const uint4*)&g_pt[0][z][bp][h][kh][0];
                const uint4* pl = (const uint4*)&g_pt[1][z][bp][h][kh][0];
                for (int i = tid; i < 768; i += 256) {
                    *(uint4*)(sm + PH_OFF + i * 16) = ph[i];
                    *(uint4*)(sm + PL_OFF + i * 16) = pl[i];
                }
            }
            if (kh == 0 && tid < 96)
                bias_s[tid] = (Mf[bp * LP + l0 + tid] != 0.f) ? 0.f : -1e6f;
            __syncthreads();

            #pragma unroll
            for (int k = 0; k < 4; k++) {
                uint32_t aqh[2][4], aql[2][4], bph[6][2], bpl[6][2];
                #pragma unroll
                for (int mi = 0; mi < 2; mi++) {
                    int row = 32 * mw + 16 * mi + a_row;
                    uint32_t off = (uint32_t)row * 256u
                                 + (uint32_t)((8 * kh + 2 * k + a_chnk) ^ (row & 7)) * 16u;
                    LDSM_X4(aqh[mi][0], aqh[mi][1], aqh[mi][2], aqh[mi][3], smb + QH_OFF + off);
                    LDSM_X4(aql[mi][0], aql[mi][1], aql[mi][2], aql[mi][3], smb + QL_OFF + off);
                }
                #pragma unroll
                for (int j = 0; j < 3; j++) {
                    int row = 48 * nw + 16 * j + b_row;
                    uint32_t off = (uint32_t)row * 128u
                                 + (uint32_t)((2 * k + b_chnk) ^ (row & 7)) * 16u;
                    LDSM_X4(bph[2*j][0], bph[2*j][1], bph[2*j+1][0], bph[2*j+1][1], smb + PH_OFF + off);
                    LDSM_X4(bpl[2*j][0], bpl[2*j][1], bpl[2*j+1][0], bpl[2*j+1][1], smb + PL_OFF + off);
                }
                #pragma unroll
                for (int mi = 0; mi < 2; mi++)
                    #pragma unroll
                    for (int t = 0; t < 6; t++) {
                        MMA_BF16(cfr[mi][t], aqh[mi], bph[t]);
                        MMA_BF16(cfr[mi][t], aqh[mi], bpl[t]);
                        MMA_BF16(cfr[mi][t], aql[mi], bph[t]);
                    }
            }
        }

        #pragma unroll
        for (int mi = 0; mi < 2; mi++) {
            float r0 = -FLT_MAX, r1 = -FLT_MAX;
            #pragma unroll
            for (int t = 0; t < 6; t++) {
                int cb = 48 * nw + 8 * t + 2 * (lane & 3);
                float b0 = bias_s[cb], b1 = bias_s[cb + 1];
                r0 = fmaxf(r0, fmaxf(cfr[mi][t][0] + b0, cfr[mi][t][1] + b1));
                r1 = fmaxf(r1, fmaxf(cfr[mi][t][2] + b0, cfr[mi][t][3] + b1));
            }
            int row0 = 32 * mw + 16 * mi + (lane >> 2);
            atomicMax(&rowmax[row0],     enc_f(r0));
            atomicMax(&rowmax[row0 + 8], enc_f(r1));
        }
    }

    __syncthreads();
    if (wid < 5) {
        int gr0 = qt * 128;
        int bq  = gr0 / 35 + wid;
        int start = max(bq * 35, gr0);
        int end   = min(bq * 35 + 35, min(gr0 + 128, MQ));
        float s = 0.f;
        for (int r = start + lane; r < end; r += 32)
            s += dec_f(rowmax[r - gr0]);
        #pragma unroll
        for (int o = 16; o > 0; o >>= 1)
            s += __shfl_xor_sync(0xffffffffu, s, o);
        if (lane == 0)
            g_part[qt][z][bp][wid] = (start < end) ? s : 0.f;
    }
}

// ===================== final per-bq assembly =====================
__global__ void final_sum_kernel(float* __restrict__ out) {
    int idx = blockIdx.x * blockDim.x + threadIdx.x;
    if (idx >= BATCH * 2 * BATCH) return;
    int bq = idx / (2 * BATCH);
    int rem = idx % (2 * BATCH);
    int z = rem / BATCH, bp = rem % BATCH;
    int t0 = (bq * 35) / 128;
    int t1 = (bq * 35 + 34) / 128;
    float s = 0.f;
    for (int t = t0; t <= t1; t++) {
        int seg = bq - (t * 128) / 35;
        if (seg >= 0 && seg < 5) s += g_part[t][z][bp][seg];
    }
    out[(size_t)bq * (2 * BATCH) + z * BATCH + bp] = s;
}

// ===================== launch =====================
extern "C" void kernel_launch(void* const* d_in, const int* in_sizes, int n_in,
                              void* d_out, int out_size)
{
    const float* qh   = (const float*)d_in[0];
    const float* ph   = (const float*)d_in[1];
    const float* nh   = (const float*)d_in[2];
    const float* W    = (const float*)d_in[3];
    const float* bias = (const float*)d_in[4];
    const void*  pm   = d_in[5];
    const void*  nm   = d_in[6];
    float* out = (float*)d_out;

    float *dpm, *dnm;
    cudaGetSymbolAddress((void**)&dpm, g_pmask);
    cudaGetSymbolAddress((void**)&dnm, g_nmask);

    detect_mode_kernel<<<1, 256>>>((const unsigned int*)pm);
    expand_mask_kernel<<<(BATCH * LP + 255) / 256, 256>>>(pm, nm);

    wt_convert_kernel<<<48, 256>>>(W);

    cudaFuncSetAttribute(proj_mma_kernel,
                         cudaFuncAttributeMaxDynamicSharedMemorySize, PJ_SMEM);
    proj_mma_kernel<<<QTILES + 2 * 135, 256, PJ_SMEM>>>(qh, ph, nh, bias);

    {
        dim3 ng((BATCH * DIM + 255) / 256, 3);
        norm_factor_kernel<<<ng, 256>>>();
    }

    qt_convert_kernel<<<QTILES, 256>>>();
    {
        dim3 pg(BATCH, 2, 2);
        pt_convert_kernel<<<pg, 256>>>();
    }

    cudaFuncSetAttribute(maxsim_mma_kernel,
                         cudaFuncAttributeMaxDynamicSharedMemorySize, MS_SMEM);
    dim3 grid(BATCH, QTILES, 2);
    maxsim_mma_kernel<<<grid, 256, MS_SMEM>>>(dpm, dnm);

    final_sum_kernel<<<(BATCH * 2 * BATCH + 255) / 256, 256>>>(out);
}

// round 13
// speedup vs baseline: 1.3571x; 1.3571x over previous
#include <cuda_runtime.h>
#include <cuda_bf16.h>
#include <cuda_fp16.h>
#include <math.h>
#include <float.h>
#include <stdint.h>

#define BATCH 96
#define NQ 35
#define LP 180
#define HID 768
#define DIM 128

#define QTILES 27            // ceil(3360/128)
#define MQ (BATCH * NQ)      // 3360
#define MP (BATCH * LP)      // 17280

// ===================== scratch (no allocation allowed) =====================
__device__ float g_q[MQ * DIM];
__device__ float g_pos[MP * DIM];
__device__ float g_neg[MP * DIM];
__device__ float g_pmask[BATCH * LP];
__device__ float g_nmask[BATCH * LP];
__device__ int   g_mask_mode;
__device__ float g_qinv[BATCH * DIM];
__device__ float g_pinv[2][BATCH * DIM];
__device__ float g_part[QTILES][2][BATCH][5];

// pre-converted fp16 tiles, ldmatrix-swizzled (256B rows, full K)
__device__ unsigned char g_qt[QTILES][32768];             // q hi only
__device__ unsigned char g_pt[2][2][BATCH][2][24576];     // [hi/lo][side][bp][half_l]
__device__ unsigned char g_wt[2][6][32768];               // W^T hi/lo per k-chunk

// ===================== helpers =====================
__device__ __forceinline__ uint32_t smem_u32(const void* p) {
    uint32_t a;
    asm("{ .reg .u64 t; cvta.to.shared.u64 t, %1; cvt.u32.u64 %0, t; }" : "=r"(a) : "l"(p));
    return a;
}

#define LDSM_X4(r0, r1, r2, r3, addr) \
    asm volatile("ldmatrix.sync.aligned.m8n8.x4.shared.b16 {%0,%1,%2,%3}, [%4];" \
        : "=r"(r0), "=r"(r1), "=r"(r2), "=r"(r3) : "r"(addr))

#define MMA_FP16(c, a, b) \
    asm volatile("mma.sync.aligned.m16n8k16.row.col.f32.f16.f16.f32 " \
        "{%0,%1,%2,%3}, {%4,%5,%6,%7}, {%8,%9}, {%0,%1,%2,%3};" \
        : "+f"((c)[0]), "+f"((c)[1]), "+f"((c)[2]), "+f"((c)[3]) \
        : "r"((a)[0]), "r"((a)[1]), "r"((a)[2]), "r"((a)[3]), \
          "r"((b)[0]), "r"((b)[1]))

__device__ __forceinline__ uint32_t pack_fp16(float f0, float f1) {
    uint16_t u0 = __half_as_ushort(__float2half_rn(f0));
    uint16_t u1 = __half_as_ushort(__float2half_rn(f1));
    return (uint32_t)u0 | ((uint32_t)u1 << 16);
}
__device__ __forceinline__ float fp16_res(float f) {   // exact in fp32
    return f - __half2float(__float2half_rn(f));
}
__device__ __forceinline__ uint4 pack_hi8(const float4& v0, const float4& v1) {
    uint4 hv;
    hv.x = pack_fp16(v0.x, v0.y); hv.y = pack_fp16(v0.z, v0.w);
    hv.z = pack_fp16(v1.x, v1.y); hv.w = pack_fp16(v1.z, v1.w);
    return hv;
}
__device__ __forceinline__ void pack8(const float4& v0, const float4& v1,
                                      uint4& hv, uint4& lv) {
    hv = pack_hi8(v0, v1);
    lv.x = pack_fp16(fp16_res(v0.x), fp16_res(v0.y));
    lv.y = pack_fp16(fp16_res(v0.z), fp16_res(v0.w));
    lv.z = pack_fp16(fp16_res(v1.x), fp16_res(v1.y));
    lv.w = pack_fp16(fp16_res(v1.z), fp16_res(v1.w));
}
__device__ __forceinline__ unsigned enc_f(float x) {
    unsigned u = __float_as_uint(x);
    return (u & 0x80000000u) ? ~u : (u | 0x80000000u);
}
__device__ __forceinline__ float dec_f(unsigned e) {
    return (e & 0x80000000u) ? __uint_as_float(e ^ 0x80000000u)
                             : __uint_as_float(~e);
}

// ===================== mask dtype detection =====================
__global__ void detect_mode_kernel(const unsigned int* __restrict__ m) {
    __shared__ int s_bf16, s_f32, s_gt1;
    if (threadIdx.x == 0) { s_bf16 = 0; s_f32 = 0; s_gt1 = 0; }
    __syncthreads();
    int lbf = 0, lf = 0, lg = 0;
    for (int i = threadIdx.x; i < (BATCH * LP) / 4; i += blockDim.x) {
        unsigned int w = m[i];
        if (w == 0x3F803F80u) lbf = 1;
        else if (w == 0x3F800000u) lf = 1;
        else if (w > 1u) lg = 1;
    }
    if (lbf) s_bf16 = 1;
    if (lf)  s_f32 = 1;
    if (lg)  s_gt1 = 1;
    __syncthreads();
    if (threadIdx.x == 0) {
        int mode;
        if (s_bf16)      mode = 3;
        else if (s_f32)  mode = 2;
        else if (s_gt1)  mode = 0;
        else             mode = 1;
        g_mask_mode = mode;
    }
}

__global__ void expand_mask_kernel(const void* __restrict__ pm, const void* __restrict__ nm) {
    int idx = blockIdx.x * blockDim.x + threadIdx.x;
    if (idx >= BATCH * LP) return;
    int mode = g_mask_mode;
    float pv, nv;
    if (mode == 0) {
        pv = ((const unsigned char*)pm)[idx] ? 1.f : 0.f;
        nv = ((const unsigned char*)nm)[idx] ? 1.f : 0.f;
    } else if (mode == 1) {
        pv = ((const int*)pm)[idx] ? 1.f : 0.f;
        nv = ((const int*)nm)[idx] ? 1.f : 0.f;
    } else if (mode == 2) {
        pv = (((const float*)pm)[idx] != 0.f) ? 1.f : 0.f;
        nv = (((const float*)nm)[idx] != 0.f) ? 1.f : 0.f;
    } else {
        pv = (__bfloat162float(((const __nv_bfloat16*)pm)[idx]) != 0.f) ? 1.f : 0.f;
        nv = (__bfloat162float(((const __nv_bfloat16*)nm)[idx]) != 0.f) ? 1.f : 0.f;
    }
    g_pmask[idx] = pv;
    g_nmask[idx] = nv;
}

// ===================== W^T -> fp16 hi/lo swizzled tiles =====================
__global__ void wt_convert_kernel(const float* __restrict__ W) {
    int idx = blockIdx.x * blockDim.x + threadIdx.x;
    if (idx >= 6 * 128 * 16) return;
    int kc = idx >> 11;
    int rem = idx & 2047;
    int d = rem >> 4, c = rem & 15;
    int h0 = kc * 128 + c * 8;
    float w[8];
    #pragma unroll
    for (int e = 0; e < 8; e++) w[e] = W[(size_t)(h0 + e) * DIM + d];
    float4 v0 = make_float4(w[0], w[1], w[2], w[3]);
    float4 v1 = make_float4(w[4], w[5], w[6], w[7]);
    uint4 hv, lv; pack8(v0, v1, hv, lv);
    uint32_t off = (uint32_t)d * 256u + (uint32_t)(c ^ (d & 7)) * 16u;
    *(uint4*)&g_wt[0][kc][off] = hv;
    *(uint4*)&g_wt[1][kc][off] = lv;
}

// ===================== merged projection GEMM (fp16 2-term) =====================
// smem: Ah 32KB | Bh 32KB | Bl 32KB = 96KB -> 2 CTAs/SM
#define PJ_AH 0
#define PJ_BH 32768
#define PJ_BL 65536
#define PJ_SMEM 98304

__global__ __launch_bounds__(256, 2) void proj_mma_kernel(
    const float* __restrict__ Aq, const float* __restrict__ Ap,
    const float* __restrict__ An, const float* __restrict__ bias)
{
    extern __shared__ char sm[];
    uint32_t smb = smem_u32(sm);
    int tid = threadIdx.x;
    int lane = tid & 31;
    int wid = tid >> 5;
    int mw = wid >> 1;
    int nw = wid & 1;

    int bx = blockIdx.x;
    const float* A; float* out; int row0, M;
    if (bx < QTILES)         { A = Aq; out = g_q;   row0 = bx * 128;              M = MQ; }
    else if (bx < QTILES+135){ A = Ap; out = g_pos; row0 = (bx-QTILES) * 128;     M = MP; }
    else                     { A = An; out = g_neg; row0 = (bx-QTILES-135) * 128; M = MP; }

    float cfr[2][8][4];
    #pragma unroll
    for (int mi = 0; mi < 2; mi++)
        #pragma unroll
        for (int t = 0; t < 8; t++)
            #pragma unroll
            for (int u = 0; u < 4; u++) cfr[mi][t][u] = 0.f;

    int a_row  = lane & 15;
    int a_chnk = lane >> 4;
    int b_row  = ((lane & 16) >> 1) + (lane & 7);
    int b_chnk = (lane >> 3) & 1;

    for (int kc = 0; kc < 6; kc++) {
        __syncthreads();
        // copy W^T hi/lo tiles (pre-converted)
        {
            const uint4* bh = (const uint4*)&g_wt[0][kc][0];
            const uint4* bl = (const uint4*)&g_wt[1][kc][0];
            for (int i = tid; i < 2048; i += 256) {
                *(uint4*)(sm + PJ_BH + i * 16) = bh[i];
                *(uint4*)(sm + PJ_BL + i * 16) = bl[i];
            }
        }
        // convert A chunk -> fp16 hi only
        for (int i = tid; i < 2048; i += 256) {
            int r = i >> 4, c = i & 15;
            int gr = row0 + r;
            float4 v0 = make_float4(0.f, 0.f, 0.f, 0.f), v1 = v0;
            if (gr < M) {
                const float* ar = A + (size_t)gr * HID + kc * 128 + c * 8;
                v0 = *(const float4*)ar;
                v1 = *(const float4*)(ar + 4);
            }
            uint32_t off = (uint32_t)r * 256u + (uint32_t)(c ^ (r & 7)) * 16u;
            *(uint4*)(sm + PJ_AH + off) = pack_hi8(v0, v1);
        }
        __syncthreads();

        #pragma unroll
        for (int k = 0; k < 8; k++) {
            uint32_t ah[2][4], bph[8][2], bpl[8][2];
            #pragma unroll
            for (int mi = 0; mi < 2; mi++) {
                int row = 32 * mw + 16 * mi + a_row;
                uint32_t off = (uint32_t)row * 256u
                             + (uint32_t)((2 * k + a_chnk) ^ (row & 7)) * 16u;
                LDSM_X4(ah[mi][0], ah[mi][1], ah[mi][2], ah[mi][3], smb + PJ_AH + off);
            }
            #pragma unroll
            for (int j = 0; j < 4; j++) {
                int row = 64 * nw + 16 * j + b_row;
                uint32_t off = (uint32_t)row * 256u
                             + (uint32_t)((2 * k + b_chnk) ^ (row & 7)) * 16u;
                LDSM_X4(bph[2*j][0], bph[2*j][1], bph[2*j+1][0], bph[2*j+1][1], smb + PJ_BH + off);
                LDSM_X4(bpl[2*j][0], bpl[2*j][1], bpl[2*j+1][0], bpl[2*j+1][1], smb + PJ_BL + off);
            }
            #pragma unroll
            for (int mi = 0; mi < 2; mi++)
                #pragma unroll
                for (int t = 0; t < 8; t++) {
                    MMA_FP16(cfr[mi][t], ah[mi], bph[t]);
                    MMA_FP16(cfr[mi][t], ah[mi], bpl[t]);
                }
        }
    }

    #pragma unroll
    for (int mi = 0; mi < 2; mi++) {
        int r0 = row0 + 32 * mw + 16 * mi + (lane >> 2);
        #pragma unroll
        for (int t = 0; t < 8; t++) {
            int col = 64 * nw + 8 * t + 2 * (lane & 3);
            float b0 = bias[col], b1 = bias[col + 1];
            if (r0 < M) {
                out[(size_t)r0 * DIM + col]     = cfr[mi][t][0] + b0;
                out[(size_t)r0 * DIM + col + 1] = cfr[mi][t][1] + b1;
            }
            if (r0 + 8 < M) {
                out[(size_t)(r0 + 8) * DIM + col]     = cfr[mi][t][2] + b0;
                out[(size_t)(r0 + 8) * DIM + col + 1] = cfr[mi][t][3] + b1;
            }
        }
    }
}

// ===================== norm factors =====================
__global__ void norm_factor_kernel() {
    int idx = blockIdx.x * blockDim.x + threadIdx.x;
    if (idx >= BATCH * DIM) return;
    int which = blockIdx.y;
    const float* src = (which == 0) ? g_q : (which == 1) ? g_pos : g_neg;
    int L = (which == 0) ? NQ : LP;
    int b = idx >> 7, d = idx & 127;
    const float* base = src + (size_t)b * L * DIM + d;
    float s = 0.f;
    for (int l = 0; l < L; l++) { float v = base[(size_t)l * DIM]; s += v * v; }
    float inv = 1.f / fmaxf(sqrtf(s), 1e-12f);
    if (which == 0) g_qinv[idx] = inv;
    else            g_pinv[which - 1][idx] = inv;
}

// ===================== tile converters (apply norm inline) =====================
__global__ void qt_convert_kernel() {
    int t = blockIdx.x;
    int tid = threadIdx.x;
    for (int i = tid; i < 128 * 16; i += 256) {
        int r = i >> 4, c = i & 15;
        int gr = t * 128 + r;
        float4 v0 = make_float4(0.f, 0.f, 0.f, 0.f), v1 = v0;
        if (gr < MQ) {
            int b = gr / 35;
            const float* qrow = g_q + (size_t)gr * DIM + c * 8;
            const float* iv = g_qinv + b * DIM + c * 8;
            float4 r0 = *(const float4*)qrow;
            float4 r1 = *(const float4*)(qrow + 4);
            float4 i0 = *(const float4*)iv;
            float4 i1 = *(const float4*)(iv + 4);
            v0 = make_float4(r0.x * i0.x, r0.y * i0.y, r0.z * i0.z, r0.w * i0.w);
            v1 = make_float4(r1.x * i1.x, r1.y * i1.y, r1.z * i1.z, r1.w * i1.w);
        }
        uint32_t off = (uint32_t)r * 256u + (uint32_t)(c ^ (r & 7)) * 16u;
        *(uint4*)&g_qt[t][off] = pack_hi8(v0, v1);
    }
}

__global__ void pt_convert_kernel() {
    int bp = blockIdx.x, h = blockIdx.y, z = blockIdx.z;
    const float* P = z ? g_neg : g_pos;
    const float* inv = g_pinv[z] + bp * DIM;
    int tid = threadIdx.x;
    int l0 = h * 84;
    for (int i = tid; i < 96 * 16; i += 256) {
        int r = i >> 4, c = i & 15;
        const float* prow = P + (size_t)(bp * LP + l0 + r) * DIM + c * 8;
        float4 r0 = *(const float4*)prow;
        float4 r1 = *(const float4*)(prow + 4);
        float4 i0 = *(const float4*)(inv + c * 8);
        float4 i1 = *(const float4*)(inv + c * 8 + 4);
        float4 v0 = make_float4(r0.x * i0.x, r0.y * i0.y, r0.z * i0.z, r0.w * i0.w);
        float4 v1 = make_float4(r1.x * i1.x, r1.y * i1.y, r1.z * i1.z, r1.w * i1.w);
        uint4 hv, lv; pack8(v0, v1, hv, lv);
        uint32_t off = (uint32_t)r * 256u + (uint32_t)(c ^ (r & 7)) * 16u;
        *(uint4*)&g_pt[0][z][bp][h][off] = hv;
        *(uint4*)&g_pt[1][z][bp][h][off] = lv;
    }
}

// ===================== mma.sync MaxSim (fp16 2-term, 80KB smem, 2 CTAs/SM) ======
#define QH_OFF 0
#define PH_OFF 32768
#define PL_OFF 57344
#define MS_SMEM 81920

__global__ __launch_bounds__(256, 2) void maxsim_mma_kernel(
    const float* __restrict__ Mpos, const float* __restrict__ Mneg)
{
    extern __shared__ char sm[];
    uint32_t smb = smem_u32(sm);
    __shared__ float    bias_s[96];
    __shared__ unsigned rowmax[128];

    int bp = blockIdx.x, qt = blockIdx.y, z = blockIdx.z;
    const float* Mf = z ? Mneg : Mpos;
    int tid  = threadIdx.x;
    int lane = tid & 31;
    int wid  = tid >> 5;
    int mw = wid >> 1;
    int nw = wid & 1;

    if (tid < 128) rowmax[tid] = 0u;

    // q hi tile: full-K, loaded once
    {
        const uint4* qh = (const uint4*)&g_qt[qt][0];
        for (int i = tid; i < 2048; i += 256)
            *(uint4*)(sm + QH_OFF + i * 16) = qh[i];
    }

    int a_row  = lane & 15;
    int a_chnk = lane >> 4;
    int b_row  = ((lane & 16) >> 1) + (lane & 7);
    int b_chnk = (lane >> 3) & 1;

    #pragma unroll
    for (int h = 0; h < 2; h++) {
        int l0 = h * 84;
        __syncthreads();

        {
            const uint4* ph = (const uint4*)&g_pt[0][z][bp][h][0];
            const uint4* pl = (const uint4*)&g_pt[1][z][bp][h][0];
            for (int i = tid; i < 1536; i += 256) {
                *(uint4*)(sm + PH_OFF + i * 16) = ph[i];
                *(uint4*)(sm + PL_OFF + i * 16) = pl[i];
            }
        }
        if (tid < 96)
            bias_s[tid] = (Mf[bp * LP + l0 + tid] != 0.f) ? 0.f : -1e6f;
        __syncthreads();

        float cfr[2][6][4];
        #pragma unroll
        for (int mi = 0; mi < 2; mi++)
            #pragma unroll
            for (int t = 0; t < 6; t++)
                #pragma unroll
                for (int u = 0; u < 4; u++) cfr[mi][t][u] = 0.f;

        #pragma unroll
        for (int k = 0; k < 8; k++) {
            uint32_t ah[2][4], bph[6][2], bpl[6][2];
            #pragma unroll
            for (int mi = 0; mi < 2; mi++) {
                int row = 32 * mw + 16 * mi + a_row;
                uint32_t off = (uint32_t)row * 256u
                             + (uint32_t)((2 * k + a_chnk) ^ (row & 7)) * 16u;
                LDSM_X4(ah[mi][0], ah[mi][1], ah[mi][2], ah[mi][3], smb + QH_OFF + off);
            }
            #pragma unroll
            for (int j = 0; j < 3; j++) {
                int row = 48 * nw + 16 * j + b_row;
                uint32_t off = (uint32_t)row * 256u
                             + (uint32_t)((2 * k + b_chnk) ^ (row & 7)) * 16u;
                LDSM_X4(bph[2*j][0], bph[2*j][1], bph[2*j+1][0], bph[2*j+1][1], smb + PH_OFF + off);
                LDSM_X4(bpl[2*j][0], bpl[2*j][1], bpl[2*j+1][0], bpl[2*j+1][1], smb + PL_OFF + off);
            }
            #pragma unroll
            for (int mi = 0; mi < 2; mi++)
                #pragma unroll
                for (int t = 0; t < 6; t++) {
                    MMA_FP16(cfr[mi][t], ah[mi], bph[t]);
                    MMA_FP16(cfr[mi][t], ah[mi], bpl[t]);
                }
        }

        #pragma unroll
        for (int mi = 0; mi < 2; mi++) {
            float r0 = -FLT_MAX, r1 = -FLT_MAX;
            #pragma unroll
            for (int t = 0; t < 6; t++) {
                int cb = 48 * nw + 8 * t + 2 * (lane & 3);
                float b0 = bias_s[cb], b1 = bias_s[cb + 1];
                r0 = fmaxf(r0, fmaxf(cfr[mi][t][0] + b0, cfr[mi][t][1] + b1));
                r1 = fmaxf(r1, fmaxf(cfr[mi][t][2] + b0, cfr[mi][t][3] + b1));
            }
            int row0 = 32 * mw + 16 * mi + (lane >> 2);
            atomicMax(&rowmax[row0],     enc_f(r0));
            atomicMax(&rowmax[row0 + 8], enc_f(r1));
        }
    }

    __syncthreads();
    if (wid < 5) {
        int gr0 = qt * 128;
        int bq  = gr0 / 35 + wid;
        int start = max(bq * 35, gr0);
        int end   = min(bq * 35 + 35, min(gr0 + 128, MQ));
        float s = 0.f;
        for (int r = start + lane; r < end; r += 32)
            s += dec_f(rowmax[r - gr0]);
        #pragma unroll
        for (int o = 16; o > 0; o >>= 1)
            s += __shfl_xor_sync(0xffffffffu, s, o);
        if (lane == 0)
            g_part[qt][z][bp][wid] = (start < end) ? s : 0.f;
    }
}

// ===================== final per-bq assembly =====================
__global__ void final_sum_kernel(float* __restrict__ out) {
    int idx = blockIdx.x * blockDim.x + threadIdx.x;
    if (idx >= BATCH * 2 * BATCH) return;
    int bq = idx / (2 * BATCH);
    int rem = idx % (2 * BATCH);
    int z = rem / BATCH, bp = rem % BATCH;
    int t0 = (bq * 35) / 128;
    int t1 = (bq * 35 + 34) / 128;
    float s = 0.f;
    for (int t = t0; t <= t1; t++) {
        int seg = bq - (t * 128) / 35;
        if (seg >= 0 && seg < 5) s += g_part[t][z][bp][seg];
    }
    out[(size_t)bq * (2 * BATCH) + z * BATCH + bp] = s;
}

// ===================== launch =====================
extern "C" void kernel_launch(void* const* d_in, const int* in_sizes, int n_in,
                              void* d_out, int out_size)
{
    const float* qh   = (const float*)d_in[0];
    const float* ph   = (const float*)d_in[1];
    const float* nh   = (const float*)d_in[2];
    const float* W    = (const float*)d_in[3];
    const float* bias = (const float*)d_in[4];
    const void*  pm   = d_in[5];
    const void*  nm   = d_in[6];
    float* out = (float*)d_out;

    float *dpm, *dnm;
    cudaGetSymbolAddress((void**)&dpm, g_pmask);
    cudaGetSymbolAddress((void**)&dnm, g_nmask);

    detect_mode_kernel<<<1, 256>>>((const unsigned int*)pm);
    expand_mask_kernel<<<(BATCH * LP + 255) / 256, 256>>>(pm, nm);

    wt_convert_kernel<<<48, 256>>>(W);

    cudaFuncSetAttribute(proj_mma_kernel,
                         cudaFuncAttributeMaxDynamicSharedMemorySize, PJ_SMEM);
    proj_mma_kernel<<<QTILES + 2 * 135, 256, PJ_SMEM>>>(qh, ph, nh, bias);

    {
        dim3 ng((BATCH * DIM + 255) / 256, 3);
        norm_factor_kernel<<<ng, 256>>>();
    }

    qt_convert_kernel<<<QTILES, 256>>>();
    {
        dim3 pg(BATCH, 2, 2);
        pt_convert_kernel<<<pg, 256>>>();
    }

    cudaFuncSetAttribute(maxsim_mma_kernel,
                         cudaFuncAttributeMaxDynamicSharedMemorySize, MS_SMEM);
    dim3 grid(BATCH, QTILES, 2);
    maxsim_mma_kernel<<<grid, 256, MS_SMEM>>>(dpm, dnm);

    final_sum_kernel<<<(BATCH * 2 * BATCH + 255) / 256, 256>>>(out);
}

// round 15
// speedup vs baseline: 1.7196x; 1.2670x over previous
#include <cuda_runtime.h>
#include <cuda_bf16.h>
#include <cuda_fp16.h>
#include <math.h>
#include <float.h>
#include <stdint.h>

#define BATCH 96
#define NQ 35
#define LP 180
#define HID 768
#define DIM 128

#define QTILES 27            // ceil(3360/128)
#define MQ (BATCH * NQ)      // 3360
#define MP (BATCH * LP)      // 17280

// ===================== scratch (no allocation allowed) =====================
__device__ float g_q[MQ * DIM];
__device__ float g_pos[MP * DIM];
__device__ float g_neg[MP * DIM];
__device__ float g_pmask[BATCH * LP];
__device__ float g_nmask[BATCH * LP];
__device__ int   g_mask_mode;
__device__ float g_qinv[BATCH * DIM];
__device__ float g_pinv[2][BATCH * DIM];
__device__ float g_part[QTILES][2][BATCH][5];

// pre-converted fp16 tiles, ldmatrix-swizzled (256B rows, full K)
__device__ unsigned char g_qt[QTILES][32768];          // q tiles (hi)
__device__ unsigned char g_pt[2][BATCH][2][24576];     // [side][bp][half_l] (hi)
__device__ unsigned char g_wt[6][32768];               // W^T per k-chunk (hi)

// ===================== helpers =====================
__device__ __forceinline__ uint32_t smem_u32(const void* p) {
    uint32_t a;
    asm("{ .reg .u64 t; cvta.to.shared.u64 t, %1; cvt.u32.u64 %0, t; }" : "=r"(a) : "l"(p));
    return a;
}

#define LDSM_X4(r0, r1, r2, r3, addr) \
    asm volatile("ldmatrix.sync.aligned.m8n8.x4.shared.b16 {%0,%1,%2,%3}, [%4];" \
        : "=r"(r0), "=r"(r1), "=r"(r2), "=r"(r3) : "r"(addr))

#define MMA_FP16(c, a, b) \
    asm volatile("mma.sync.aligned.m16n8k16.row.col.f32.f16.f16.f32 " \
        "{%0,%1,%2,%3}, {%4,%5,%6,%7}, {%8,%9}, {%0,%1,%2,%3};" \
        : "+f"((c)[0]), "+f"((c)[1]), "+f"((c)[2]), "+f"((c)[3]) \
        : "r"((a)[0]), "r"((a)[1]), "r"((a)[2]), "r"((a)[3]), \
          "r"((b)[0]), "r"((b)[1]))

__device__ __forceinline__ uint32_t pack_fp16(float f0, float f1) {
    uint16_t u0 = __half_as_ushort(__float2half_rn(f0));
    uint16_t u1 = __half_as_ushort(__float2half_rn(f1));
    return (uint32_t)u0 | ((uint32_t)u1 << 16);
}
__device__ __forceinline__ uint4 pack_hi8(const float4& v0, const float4& v1) {
    uint4 hv;
    hv.x = pack_fp16(v0.x, v0.y); hv.y = pack_fp16(v0.z, v0.w);
    hv.z = pack_fp16(v1.x, v1.y); hv.w = pack_fp16(v1.z, v1.w);
    return hv;
}
__device__ __forceinline__ unsigned enc_f(float x) {
    unsigned u = __float_as_uint(x);
    return (u & 0x80000000u) ? ~u : (u | 0x80000000u);
}
__device__ __forceinline__ float dec_f(unsigned e) {
    return (e & 0x80000000u) ? __uint_as_float(e ^ 0x80000000u)
                             : __uint_as_float(~e);
}

// ===================== mask dtype detection =====================
__global__ void detect_mode_kernel(const unsigned int* __restrict__ m) {
    __shared__ int s_bf16, s_f32, s_gt1;
    if (threadIdx.x == 0) { s_bf16 = 0; s_f32 = 0; s_gt1 = 0; }
    __syncthreads();
    int lbf = 0, lf = 0, lg = 0;
    for (int i = threadIdx.x; i < (BATCH * LP) / 4; i += blockDim.x) {
        unsigned int w = m[i];
        if (w == 0x3F803F80u) lbf = 1;
        else if (w == 0x3F800000u) lf = 1;
        else if (w > 1u) lg = 1;
    }
    if (lbf) s_bf16 = 1;
    if (lf)  s_f32 = 1;
    if (lg)  s_gt1 = 1;
    __syncthreads();
    if (threadIdx.x == 0) {
        int mode;
        if (s_bf16)      mode = 3;
        else if (s_f32)  mode = 2;
        else if (s_gt1)  mode = 0;
        else             mode = 1;
        g_mask_mode = mode;
    }
}

__global__ void expand_mask_kernel(const void* __restrict__ pm, const void* __restrict__ nm) {
    int idx = blockIdx.x * blockDim.x + threadIdx.x;
    if (idx >= BATCH * LP) return;
    int mode = g_mask_mode;
    float pv, nv;
    if (mode == 0) {
        pv = ((const unsigned char*)pm)[idx] ? 1.f : 0.f;
        nv = ((const unsigned char*)nm)[idx] ? 1.f : 0.f;
    } else if (mode == 1) {
        pv = ((const int*)pm)[idx] ? 1.f : 0.f;
        nv = ((const int*)nm)[idx] ? 1.f : 0.f;
    } else if (mode == 2) {
        pv = (((const float*)pm)[idx] != 0.f) ? 1.f : 0.f;
        nv = (((const float*)nm)[idx] != 0.f) ? 1.f : 0.f;
    } else {
        pv = (__bfloat162float(((const __nv_bfloat16*)pm)[idx]) != 0.f) ? 1.f : 0.f;
        nv = (__bfloat162float(((const __nv_bfloat16*)nm)[idx]) != 0.f) ? 1.f : 0.f;
    }
    g_pmask[idx] = pv;
    g_nmask[idx] = nv;
}

// ===================== W^T -> fp16 swizzled tiles (hi only) =====================
__global__ void wt_convert_kernel(const float* __restrict__ W) {
    int idx = blockIdx.x * blockDim.x + threadIdx.x;
    if (idx >= 6 * 128 * 16) return;
    int kc = idx >> 11;
    int rem = idx & 2047;
    int d = rem >> 4, c = rem & 15;
    int h0 = kc * 128 + c * 8;
    float w[8];
    #pragma unroll
    for (int e = 0; e < 8; e++) w[e] = W[(size_t)(h0 + e) * DIM + d];
    float4 v0 = make_float4(w[0], w[1], w[2], w[3]);
    float4 v1 = make_float4(w[4], w[5], w[6], w[7]);
    uint32_t off = (uint32_t)d * 256u + (uint32_t)(c ^ (d & 7)) * 16u;
    *(uint4*)&g_wt[kc][off] = pack_hi8(v0, v1);
}

// ===================== merged projection GEMM (fp16 1-term) =====================
// smem: Ah 32KB | Bh 32KB = 64KB
#define PJ_AH 0
#define PJ_BH 32768
#define PJ_SMEM 65536

__global__ __launch_bounds__(256, 2) void proj_mma_kernel(
    const float* __restrict__ Aq, const float* __restrict__ Ap,
    const float* __restrict__ An, const float* __restrict__ bias)
{
    extern __shared__ char sm[];
    uint32_t smb = smem_u32(sm);
    int tid = threadIdx.x;
    int lane = tid & 31;
    int wid = tid >> 5;
    int mw = wid >> 1;
    int nw = wid & 1;

    int bx = blockIdx.x;
    const float* A; float* out; int row0, M;
    if (bx < QTILES)         { A = Aq; out = g_q;   row0 = bx * 128;              M = MQ; }
    else if (bx < QTILES+135){ A = Ap; out = g_pos; row0 = (bx-QTILES) * 128;     M = MP; }
    else                     { A = An; out = g_neg; row0 = (bx-QTILES-135) * 128; M = MP; }

    float cfr[2][8][4];
    #pragma unroll
    for (int mi = 0; mi < 2; mi++)
        #pragma unroll
        for (int t = 0; t < 8; t++)
            #pragma unroll
            for (int u = 0; u < 4; u++) cfr[mi][t][u] = 0.f;

    int a_row  = lane & 15;
    int a_chnk = lane >> 4;
    int b_row  = ((lane & 16) >> 1) + (lane & 7);
    int b_chnk = (lane >> 3) & 1;

    for (int kc = 0; kc < 6; kc++) {
        __syncthreads();
        // copy W^T hi tile (pre-converted)
        {
            const uint4* bh = (const uint4*)&g_wt[kc][0];
            for (int i = tid; i < 2048; i += 256)
                *(uint4*)(sm + PJ_BH + i * 16) = bh[i];
        }
        // convert A chunk -> fp16 hi
        for (int i = tid; i < 2048; i += 256) {
            int r = i >> 4, c = i & 15;
            int gr = row0 + r;
            float4 v0 = make_float4(0.f, 0.f, 0.f, 0.f), v1 = v0;
            if (gr < M) {
                const float* ar = A + (size_t)gr * HID + kc * 128 + c * 8;
                v0 = *(const float4*)ar;
                v1 = *(const float4*)(ar + 4);
            }
            uint32_t off = (uint32_t)r * 256u + (uint32_t)(c ^ (r & 7)) * 16u;
            *(uint4*)(sm + PJ_AH + off) = pack_hi8(v0, v1);
        }
        __syncthreads();

        #pragma unroll
        for (int k = 0; k < 8; k++) {
            uint32_t ah[2][4], bph[8][2];
            #pragma unroll
            for (int mi = 0; mi < 2; mi++) {
                int row = 32 * mw + 16 * mi + a_row;
                uint32_t off = (uint32_t)row * 256u
                             + (uint32_t)((2 * k + a_chnk) ^ (row & 7)) * 16u;
                LDSM_X4(ah[mi][0], ah[mi][1], ah[mi][2], ah[mi][3], smb + PJ_AH + off);
            }
            #pragma unroll
            for (int j = 0; j < 4; j++) {
                int row = 64 * nw + 16 * j + b_row;
                uint32_t off = (uint32_t)row * 256u
                             + (uint32_t)((2 * k + b_chnk) ^ (row & 7)) * 16u;
                LDSM_X4(bph[2*j][0], bph[2*j][1], bph[2*j+1][0], bph[2*j+1][1], smb + PJ_BH + off);
            }
            #pragma unroll
            for (int mi = 0; mi < 2; mi++)
                #pragma unroll
                for (int t = 0; t < 8; t++)
                    MMA_FP16(cfr[mi][t], ah[mi], bph[t]);
        }
    }

    #pragma unroll
    for (int mi = 0; mi < 2; mi++) {
        int r0 = row0 + 32 * mw + 16 * mi + (lane >> 2);
        #pragma unroll
        for (int t = 0; t < 8; t++) {
            int col = 64 * nw + 8 * t + 2 * (lane & 3);
            float b0 = bias[col], b1 = bias[col + 1];
            if (r0 < M) {
                out[(size_t)r0 * DIM + col]     = cfr[mi][t][0] + b0;
                out[(size_t)r0 * DIM + col + 1] = cfr[mi][t][1] + b1;
            }
            if (r0 + 8 < M) {
                out[(size_t)(r0 + 8) * DIM + col]     = cfr[mi][t][2] + b0;
                out[(size_t)(r0 + 8) * DIM + col + 1] = cfr[mi][t][3] + b1;
            }
        }
    }
}

// ===================== norm factors =====================
__global__ void norm_factor_kernel() {
    int idx = blockIdx.x * blockDim.x + threadIdx.x;
    if (idx >= BATCH * DIM) return;
    int which = blockIdx.y;
    const float* src = (which == 0) ? g_q : (which == 1) ? g_pos : g_neg;
    int L = (which == 0) ? NQ : LP;
    int b = idx >> 7, d = idx & 127;
    const float* base = src + (size_t)b * L * DIM + d;
    float s = 0.f;
    for (int l = 0; l < L; l++) { float v = base[(size_t)l * DIM]; s += v * v; }
    float inv = 1.f / fmaxf(sqrtf(s), 1e-12f);
    if (which == 0) g_qinv[idx] = inv;
    else            g_pinv[which - 1][idx] = inv;
}

// ===================== tile converters (apply norm inline, hi only) ==============
__global__ void qt_convert_kernel() {
    int t = blockIdx.x;
    int tid = threadIdx.x;
    for (int i = tid; i < 128 * 16; i += 256) {
        int r = i >> 4, c = i & 15;
        int gr = t * 128 + r;
        float4 v0 = make_float4(0.f, 0.f, 0.f, 0.f), v1 = v0;
        if (gr < MQ) {
            int b = gr / 35;
            const float* qrow = g_q + (size_t)gr * DIM + c * 8;
            const float* iv = g_qinv + b * DIM + c * 8;
            float4 r0 = *(const float4*)qrow;
            float4 r1 = *(const float4*)(qrow + 4);
            float4 i0 = *(const float4*)iv;
            float4 i1 = *(const float4*)(iv + 4);
            v0 = make_float4(r0.x * i0.x, r0.y * i0.y, r0.z * i0.z, r0.w * i0.w);
            v1 = make_float4(r1.x * i1.x, r1.y * i1.y, r1.z * i1.z, r1.w * i1.w);
        }
        uint32_t off = (uint32_t)r * 256u + (uint32_t)(c ^ (r & 7)) * 16u;
        *(uint4*)&g_qt[t][off] = pack_hi8(v0, v1);
    }
}

__global__ void pt_convert_kernel() {
    int bp = blockIdx.x, h = blockIdx.y, z = blockIdx.z;
    const float* P = z ? g_neg : g_pos;
    const float* inv = g_pinv[z] + bp * DIM;
    int tid = threadIdx.x;
    int l0 = h * 84;
    for (int i = tid; i < 96 * 16; i += 256) {
        int r = i >> 4, c = i & 15;
        const float* prow = P + (size_t)(bp * LP + l0 + r) * DIM + c * 8;
        float4 r0 = *(const float4*)prow;
        float4 r1 = *(const float4*)(prow + 4);
        float4 i0 = *(const float4*)(inv + c * 8);
        float4 i1 = *(const float4*)(inv + c * 8 + 4);
        float4 v0 = make_float4(r0.x * i0.x, r0.y * i0.y, r0.z * i0.z, r0.w * i0.w);
        float4 v1 = make_float4(r1.x * i1.x, r1.y * i1.y, r1.z * i1.z, r1.w * i1.w);
        uint32_t off = (uint32_t)r * 256u + (uint32_t)(c ^ (r & 7)) * 16u;
        *(uint4*)&g_pt[z][bp][h][off] = pack_hi8(v0, v1);
    }
}

// ===================== mma.sync MaxSim (fp16 1-term, 56KB smem) ==================
#define QH_OFF 0
#define PH_OFF 32768
#define MS_SMEM 57344

__global__ __launch_bounds__(256, 2) void maxsim_mma_kernel(
    const float* __restrict__ Mpos, const float* __restrict__ Mneg)
{
    extern __shared__ char sm[];
    uint32_t smb = smem_u32(sm);
    __shared__ float    bias_s[96];
    __shared__ unsigned rowmax[128];

    int bp = blockIdx.x, qt = blockIdx.y, z = blockIdx.z;
    const float* Mf = z ? Mneg : Mpos;
    int tid  = threadIdx.x;
    int lane = tid & 31;
    int wid  = tid >> 5;
    int mw = wid >> 1;
    int nw = wid & 1;

    if (tid < 128) rowmax[tid] = 0u;

    // q hi tile: full-K, loaded once
    {
        const uint4* qh = (const uint4*)&g_qt[qt][0];
        for (int i = tid; i < 2048; i += 256)
            *(uint4*)(sm + QH_OFF + i * 16) = qh[i];
    }

    int a_row  = lane & 15;
    int a_chnk = lane >> 4;
    int b_row  = ((lane & 16) >> 1) + (lane & 7);
    int b_chnk = (lane >> 3) & 1;

    #pragma unroll
    for (int h = 0; h < 2; h++) {
        int l0 = h * 84;
        __syncthreads();

        {
            const uint4* ph = (const uint4*)&g_pt[z][bp][h][0];
            for (int i = tid; i < 1536; i += 256)
                *(uint4*)(sm + PH_OFF + i * 16) = ph[i];
        }
        if (tid < 96)
            bias_s[tid] = (Mf[bp * LP + l0 + tid] != 0.f) ? 0.f : -1e6f;
        __syncthreads();

        float cfr[2][6][4];
        #pragma unroll
        for (int mi = 0; mi < 2; mi++)
            #pragma unroll
            for (int t = 0; t < 6; t++)
                #pragma unroll
                for (int u = 0; u < 4; u++) cfr[mi][t][u] = 0.f;

        #pragma unroll
        for (int k = 0; k < 8; k++) {
            uint32_t ah[2][4], bph[6][2];
            #pragma unroll
            for (int mi = 0; mi < 2; mi++) {
                int row = 32 * mw + 16 * mi + a_row;
                uint32_t off = (uint32_t)row * 256u
                             + (uint32_t)((2 * k + a_chnk) ^ (row & 7)) * 16u;
                LDSM_X4(ah[mi][0], ah[mi][1], ah[mi][2], ah[mi][3], smb + QH_OFF + off);
            }
            #pragma unroll
            for (int j = 0; j < 3; j++) {
                int row = 48 * nw + 16 * j + b_row;
                uint32_t off = (uint32_t)row * 256u
                             + (uint32_t)((2 * k + b_chnk) ^ (row & 7)) * 16u;
                LDSM_X4(bph[2*j][0], bph[2*j][1], bph[2*j+1][0], bph[2*j+1][1], smb + PH_OFF + off);
            }
            #pragma unroll
            for (int mi = 0; mi < 2; mi++)
                #pragma unroll
                for (int t = 0; t < 6; t++)
                    MMA_FP16(cfr[mi][t], ah[mi], bph[t]);
        }

        #pragma unroll
        for (int mi = 0; mi < 2; mi++) {
            float r0 = -FLT_MAX, r1 = -FLT_MAX;
            #pragma unroll
            for (int t = 0; t < 6; t++) {
                int cb = 48 * nw + 8 * t + 2 * (lane & 3);
                float b0 = bias_s[cb], b1 = bias_s[cb + 1];
                r0 = fmaxf(r0, fmaxf(cfr[mi][t][0] + b0, cfr[mi][t][1] + b1));
                r1 = fmaxf(r1, fmaxf(cfr[mi][t][2] + b0, cfr[mi][t][3] + b1));
            }
            int row0 = 32 * mw + 16 * mi + (lane >> 2);
            atomicMax(&rowmax[row0],     enc_f(r0));
            atomicMax(&rowmax[row0 + 8], enc_f(r1));
        }
    }

    __syncthreads();
    if (wid < 5) {
        int gr0 = qt * 128;
        int bq  = gr0 / 35 + wid;
        int start = max(bq * 35, gr0);
        int end   = min(bq * 35 + 35, min(gr0 + 128, MQ));
        float s = 0.f;
        for (int r = start + lane; r < end; r += 32)
            s += dec_f(rowmax[r - gr0]);
        #pragma unroll
        for (int o = 16; o > 0; o >>= 1)
            s += __shfl_xor_sync(0xffffffffu, s, o);
        if (lane == 0)
            g_part[qt][z][bp][wid] = (start < end) ? s : 0.f;
    }
}

// ===================== final per-bq assembly =====================
__global__ void final_sum_kernel(float* __restrict__ out) {
    int idx = blockIdx.x * blockDim.x + threadIdx.x;
    if (idx >= BATCH * 2 * BATCH) return;
    int bq = idx / (2 * BATCH);
    int rem = idx % (2 * BATCH);
    int z = rem / BATCH, bp = rem % BATCH;
    int t0 = (bq * 35) / 128;
    int t1 = (bq * 35 + 34) / 128;
    float s = 0.f;
    for (int t = t0; t <= t1; t++) {
        int seg = bq - (t * 128) / 35;
        if (seg >= 0 && seg < 5) s += g_part[t][z][bp][seg];
    }
    out[(size_t)bq * (2 * BATCH) + z * BATCH + bp] = s;
}

// ===================== launch =====================
extern "C" void kernel_launch(void* const* d_in, const int* in_sizes, int n_in,
                              void* d_out, int out_size)
{
    const float* qh   = (const float*)d_in[0];
    const float* ph   = (const float*)d_in[1];
    const float* nh   = (const float*)d_in[2];
    const float* W    = (const float*)d_in[3];
    const float* bias = (const float*)d_in[4];
    const void*  pm   = d_in[5];
    const void*  nm   = d_in[6];
    float* out = (float*)d_out;

    float *dpm, *dnm;
    cudaGetSymbolAddress((void**)&dpm, g_pmask);
    cudaGetSymbolAddress((void**)&dnm, g_nmask);

    detect_mode_kernel<<<1, 256>>>((const unsigned int*)pm);
    expand_mask_kernel<<<(BATCH * LP + 255) / 256, 256>>>(pm, nm);

    wt_convert_kernel<<<48, 256>>>(W);

    cudaFuncSetAttribute(proj_mma_kernel,
                         cudaFuncAttributeMaxDynamicSharedMemorySize, PJ_SMEM);
    proj_mma_kernel<<<QTILES + 2 * 135, 256, PJ_SMEM>>>(qh, ph, nh, bias);

    {
        dim3 ng((BATCH * DIM + 255) / 256, 3);
        norm_factor_kernel<<<ng, 256>>>();
    }

    qt_convert_kernel<<<QTILES, 256>>>();
    {
        dim3 pg(BATCH, 2, 2);
        pt_convert_kernel<<<pg, 256>>>();
    }

    cudaFuncSetAttribute(maxsim_mma_kernel,
                         cudaFuncAttributeMaxDynamicSharedMemorySize, MS_SMEM);
    dim3 grid(BATCH, QTILES, 2);
    maxsim_mma_kernel<<<grid, 256, MS_SMEM>>>(dpm, dnm);

    final_sum_kernel<<<(BATCH * 2 * BATCH + 255) / 256, 256>>>(out);
}